// round 5
// baseline (speedup 1.0000x reference)
#include <cuda_runtime.h>
#include <math.h>

#define IN_DIM 128
#define HID    64
#define HID4   16
#define NMAX   50176
#define EMAX   800256
#define CSR_BLKS 200
#define CSR_THR  256
#define XS_STRIDE 130          // even (8B align) + conflict-free strided reads

// ---------------- device scratch (no allocations allowed) -----------------
// Self-restoring: d_deg (reset in scan phase), d_cnt (reset in agg2),
// d_bar (reset in agg1). Zero-initialized on first call.
__device__ float d_deg [NMAX];
__device__ int   d_cnt [NMAX];
__device__ float d_dinv[NMAX];
__device__ int   d_excl[NMAX];          // (unused slot kept for layout stability)
__device__ int   d_bsum[256];
__device__ int   d_start[NMAX];
__device__ int   d_cursor[NMAX];
__device__ int2  d_csr[EMAX];           // {src, ew*dinv[src] as bits}, grouped by dst
__device__ float d_h  [(size_t)NMAX * HID];   // x @ W1 (raw)
__device__ float d_z  [NMAX];                 // relu(h1) @ W2 (raw)
__device__ int   d_bar[4];              // grid-barrier arrive counters

// -------- edge-index width detection (int64 vs int32) ---------------------
__device__ __forceinline__ bool is_i64(const int* ei) {
    return (ei[1] | ei[3] | ei[5] | ei[7]) == 0;
}
__device__ __forceinline__ void load_edge(const int* ei, int E, int e,
                                          bool i64, int& s, int& d) {
    if (i64) {
        const long long* p = (const long long*)ei;
        s = (int)p[e]; d = (int)p[E + e];
    } else {
        s = ei[e]; d = ei[E + e];
    }
}

// -------- software grid barrier among CSR_BLKS co-resident blocks ---------
__device__ __forceinline__ void grid_bar(int i) {
    __syncthreads();
    if (threadIdx.x == 0) {
        __threadfence();
        atomicAdd(&d_bar[i], 1);
        while (((volatile int*)d_bar)[i] < CSR_BLKS) { __nanosleep(64); }
    }
    __syncthreads();
}

// ======== K1: CSR build — count | scan | finalize | fill (one launch) ======
__global__ __launch_bounds__(CSR_THR)
void k_csr(const int* __restrict__ ei, const float* __restrict__ ew,
           int N, int E) {
    int tid = threadIdx.x;
    int bid = blockIdx.x;
    bool i64 = is_i64(ei);
    __shared__ int sh[CSR_THR];

    // ---- phase 0: weighted degree + edge count ----
    for (int e = bid * CSR_THR + tid; e < E; e += CSR_BLKS * CSR_THR) {
        int s, d; load_edge(ei, E, e, i64, s, d);
        (void)s;
        atomicAdd(&d_deg[d], ew[e]);
        atomicAdd(&d_cnt[d], 1);
    }
    grid_bar(0);

    // ---- phase 1: per-chunk (256-wide) inclusive scan of counts ----
    int nch = (N + 255) >> 8;               // 196 chunks, CSR_BLKS >= nch
    int myv = 0, incl = 0;
    if (bid < nch) {
        int n = bid * 256 + tid;
        myv = (n < N) ? __ldcg(&d_cnt[n]) : 0;
        sh[tid] = myv;
        __syncthreads();
        #pragma unroll
        for (int off = 1; off < CSR_THR; off <<= 1) {
            int t = (tid >= off) ? sh[tid - off] : 0;
            __syncthreads();
            sh[tid] += t;
            __syncthreads();
        }
        incl = sh[tid];
        if (tid == CSR_THR - 1) d_bsum[bid] = incl;
    }
    grid_bar(1);

    // ---- phase 2: base = sum of bsum[0..bid-1] (block reduce); finalize ----
    if (bid < nch) {
        int v = (tid < bid) ? __ldcg(&d_bsum[tid]) : 0;
        sh[tid] = v;
        __syncthreads();
        #pragma unroll
        for (int o = 128; o > 0; o >>= 1) {
            if (tid < o) sh[tid] += sh[tid + o];
            __syncthreads();
        }
        int base = sh[0];
        int n = bid * 256 + tid;
        if (n < N) {
            int start = base + (incl - myv);
            d_start[n]  = start;
            d_cursor[n] = start;
            d_dinv[n]   = rsqrtf(1.0f + __ldcg(&d_deg[n]));
            d_deg[n]    = 0.0f;              // restore for next replay
        }
    }
    grid_bar(2);

    // ---- phase 3: fill CSR with w' = ew * dinv[src] ----
    for (int e = bid * CSR_THR + tid; e < E; e += CSR_BLKS * CSR_THR) {
        int s, d; load_edge(ei, E, e, i64, s, d);
        float w = ew[e] * __ldcg(&d_dinv[s]);
        int slot = atomicAdd(&d_cursor[d], 1);
        d_csr[slot] = make_int2(s, __float_as_int(w));
    }
}

// ======== K2: GEMM h = x @ W1, f32x2 FFMA2, 128 rows/block =================
__device__ __forceinline__ unsigned long long pack2(float a, float b) {
    unsigned long long r;
    asm("mov.b64 %0, {%1, %2};" : "=l"(r) : "f"(a), "f"(b));
    return r;
}
__device__ __forceinline__ void fma2(unsigned long long& d,
                                     unsigned long long a, unsigned long long b) {
    asm("fma.rn.f32x2 %0, %1, %2, %0;" : "+l"(d) : "l"(a), "l"(b));
}
__device__ __forceinline__ void unpack2(unsigned long long v, float& a, float& b) {
    asm("mov.b64 {%0, %1}, %2;" : "=f"(a), "=f"(b) : "l"(v));
}

extern __shared__ float smem_dyn[];
#define GEMM_SMEM ((IN_DIM * HID + IN_DIM * XS_STRIDE) * 4)

__global__ void __launch_bounds__(128, 2)
k_gemm(const float* __restrict__ x, const float* __restrict__ W1, int N) {
    float* Ws = smem_dyn;                       // [128][64]
    float* xs = smem_dyn + IN_DIM * HID;        // [128][XS_STRIDE]
    int tid = threadIdx.x;
    int row0 = blockIdx.x * 128;

    #pragma unroll
    for (int i = 0; i < 16; i++)
        ((float4*)Ws)[tid + i * 128] = ((const float4*)W1)[tid + i * 128];

    // x tile load (coalesced) -> smem row-major, stride XS_STRIDE
    #pragma unroll
    for (int i = 0; i < 32; i++) {
        int idx = tid + i * 128;
        int r   = idx >> 5;                    // 0..127
        int k4  = idx & 31;
        float4 v = make_float4(0.f, 0.f, 0.f, 0.f);
        int row = row0 + r;
        if (row < N) v = ((const float4*)x)[(size_t)row * 32 + k4];
        float2* p = (float2*)&xs[r * XS_STRIDE + 4 * k4];
        p[0] = make_float2(v.x, v.y);
        p[1] = make_float2(v.z, v.w);
    }
    __syncthreads();

    int cg = tid & 7;       // 8 col groups x 8 cols
    int rg = tid >> 3;      // 16 row groups; thread rows: rg + 16*j
    unsigned long long acc[8][4];
    #pragma unroll
    for (int j = 0; j < 8; j++)
        #pragma unroll
        for (int p = 0; p < 4; p++) acc[j][p] = 0ULL;

    #pragma unroll 2
    for (int k = 0; k < IN_DIM; k++) {
        const unsigned long long* wp =
            (const unsigned long long*)&Ws[k * HID + 8 * cg];
        unsigned long long w0 = wp[0], w1 = wp[1], w2 = wp[2], w3 = wp[3];
        #pragma unroll
        for (int j = 0; j < 8; j++) {
            float xv = xs[(rg + 16 * j) * XS_STRIDE + k];
            unsigned long long xx = pack2(xv, xv);
            fma2(acc[j][0], xx, w0);
            fma2(acc[j][1], xx, w1);
            fma2(acc[j][2], xx, w2);
            fma2(acc[j][3], xx, w3);
        }
    }

    #pragma unroll
    for (int j = 0; j < 8; j++) {
        int row = row0 + rg + 16 * j;
        if (row < N) {
            float2* dst = (float2*)&d_h[(size_t)row * HID + 8 * cg];
            #pragma unroll
            for (int p = 0; p < 4; p++) {
                float a, b; unpack2(acc[j][p], a, b);
                dst[p] = make_float2(a, b);
            }
        }
    }
}

// ======== K3: layer-1 gather + bias + ReLU + @W2 (fused); reset d_bar ======
__global__ __launch_bounds__(256)
void k_agg1(const float* __restrict__ b1, const float* __restrict__ W2, int N) {
    if (blockIdx.x == 0 && threadIdx.x < 4) d_bar[threadIdx.x] = 0;  // restore

    int t = blockIdx.x * blockDim.x + threadIdx.x;
    int n = t >> 4;
    int c = t & 15;
    bool valid = (n < N);
    if (!valid) n = 0;

    int st  = d_start[n];
    int cnt = d_cnt[n];
    float di = d_dinv[n];
    const float4* h4 = (const float4*)d_h;

    float4 self = h4[(size_t)n * HID4 + c];
    float4 acc = make_float4(di * self.x, di * self.y, di * self.z, di * self.w);

    int j = 0;
    for (; j + 4 <= cnt; j += 4) {
        int2 e0 = d_csr[st + j];
        int2 e1 = d_csr[st + j + 1];
        int2 e2 = d_csr[st + j + 2];
        int2 e3 = d_csr[st + j + 3];
        float4 v0 = h4[(size_t)e0.x * HID4 + c];
        float4 v1 = h4[(size_t)e1.x * HID4 + c];
        float4 v2 = h4[(size_t)e2.x * HID4 + c];
        float4 v3 = h4[(size_t)e3.x * HID4 + c];
        float w0 = __int_as_float(e0.y), w1 = __int_as_float(e1.y);
        float w2 = __int_as_float(e2.y), w3 = __int_as_float(e3.y);
        acc.x = fmaf(w0, v0.x, fmaf(w1, v1.x, fmaf(w2, v2.x, fmaf(w3, v3.x, acc.x))));
        acc.y = fmaf(w0, v0.y, fmaf(w1, v1.y, fmaf(w2, v2.y, fmaf(w3, v3.y, acc.y))));
        acc.z = fmaf(w0, v0.z, fmaf(w1, v1.z, fmaf(w2, v2.z, fmaf(w3, v3.z, acc.z))));
        acc.w = fmaf(w0, v0.w, fmaf(w1, v1.w, fmaf(w2, v2.w, fmaf(w3, v3.w, acc.w))));
    }
    for (; j < cnt; j++) {
        int2 e = d_csr[st + j];
        float4 v = h4[(size_t)e.x * HID4 + c];
        float w = __int_as_float(e.y);
        acc.x = fmaf(w, v.x, acc.x);
        acc.y = fmaf(w, v.y, acc.y);
        acc.z = fmaf(w, v.z, acc.z);
        acc.w = fmaf(w, v.w, acc.w);
    }

    float4 bb = ((const float4*)b1)[c];
    float4 v;
    v.x = fmaxf(fmaf(di, acc.x, bb.x), 0.f);
    v.y = fmaxf(fmaf(di, acc.y, bb.y), 0.f);
    v.z = fmaxf(fmaf(di, acc.z, bb.z), 0.f);
    v.w = fmaxf(fmaf(di, acc.w, bb.w), 0.f);
    float4 w2 = ((const float4*)W2)[c];
    float p = v.x * w2.x + v.y * w2.y + v.z * w2.z + v.w * w2.w;
    p += __shfl_xor_sync(0xffffffffu, p, 8);
    p += __shfl_xor_sync(0xffffffffu, p, 4);
    p += __shfl_xor_sync(0xffffffffu, p, 2);
    p += __shfl_xor_sync(0xffffffffu, p, 1);
    if (valid && c == 0) d_z[n] = p;
}

// ======== K4: layer-2 gather + sigmoid + output; reset d_cnt ================
__global__ void k_agg2(const float* __restrict__ b2, float* __restrict__ out, int N) {
    int warp = (blockIdx.x * blockDim.x + threadIdx.x) >> 5;
    int lane = threadIdx.x & 31;
    if (warp >= N) return;
    int st  = d_start[warp];
    int cnt = d_cnt[warp];
    float acc = 0.f;
    for (int j = lane; j < cnt; j += 32) {
        int2 e = d_csr[st + j];
        acc += __int_as_float(e.y) * d_z[e.x];
    }
    #pragma unroll
    for (int off = 16; off > 0; off >>= 1)
        acc += __shfl_xor_sync(0xffffffffu, acc, off);
    if (lane == 0) {
        float di = d_dinv[warp];
        float t = fmaf(di, acc + di * d_z[warp], b2[0]);
        out[warp] = 1.0f / (1.0f + expf(-t));
        d_cnt[warp] = 0;                    // restore for next replay
    }
}

// ---------------- launcher --------------------------------------------------
extern "C" void kernel_launch(void* const* d_in, const int* in_sizes, int n_in,
                              void* d_out, int out_size) {
    const float* x  = (const float*)d_in[0];
    const int*   ei = (const int*)d_in[1];
    const float* ew = (const float*)d_in[2];
    const float* W1 = (const float*)d_in[3];
    const float* b1 = (const float*)d_in[4];
    const float* W2 = (const float*)d_in[5];
    const float* b2 = (const float*)d_in[6];
    float* out = (float*)d_out;

    int N = in_sizes[0] / IN_DIM;   // 50000
    int E = in_sizes[2];            // 800000

    cudaFuncSetAttribute(k_gemm, cudaFuncAttributeMaxDynamicSharedMemorySize,
                         GEMM_SMEM);

    k_csr <<<CSR_BLKS, CSR_THR>>>(ei, ew, N, E);
    k_gemm<<<(N + 127) / 128, 128, GEMM_SMEM>>>(x, W1, N);
    k_agg1<<<(N * 16 + 255) / 256, 256>>>(b1, W2, N);
    k_agg2<<<(N * 32 + 255) / 256, 256>>>(b2, out, N);
}

// round 6
// speedup vs baseline: 1.2004x; 1.2004x over previous
#include <cuda_runtime.h>
#include <math.h>

#define IN_DIM 128
#define HID    64
#define HID4   16
#define NMAX   50176
#define EMAX   800256
#define XS_STRIDE 130
#define DEG_SCALE 1048576.0f          // 2^20 fixed-point for weighted degree

// ---------------- device scratch (no allocations allowed) -----------------
// Self-restoring invariant: d_degcnt, d_cnt, d_total are zero at the START
// of every kernel_launch call (zero-init on first call; last consumer resets).
__device__ unsigned long long d_degcnt[NMAX]; // {cnt:24 | deg_fixed:40}
__device__ int   d_cnt [NMAX];
__device__ float d_dinv[NMAX];
__device__ int   d_start[NMAX];
__device__ int   d_cursor[NMAX];
__device__ int   d_total;
__device__ int2  d_csr[EMAX];                 // {src, ew bits}, grouped by dst
__device__ float d_g  [(size_t)NMAX * HID];   // (x @ W1) * dinv[row]
__device__ float d_g2 [NMAX];                 // (relu(h1) @ W2) * dinv[row]

// -------- edge-index width detection (int64 vs int32) ---------------------
__device__ __forceinline__ bool is_i64(const int* ei) {
    return (ei[1] | ei[3] | ei[5] | ei[7]) == 0;
}
__device__ __forceinline__ void load_edge(const int* ei, int E, int e,
                                          bool i64, int& s, int& d) {
    if (i64) {
        const long long* p = (const long long*)ei;
        s = (int)p[e]; d = (int)p[E + e];
    } else {
        s = ei[e]; d = ei[E + e];
    }
}

// ======== K1: count — ONE u64 atomic per edge ==============================
__global__ void k_count(const int* __restrict__ ei,
                        const float* __restrict__ ew, int E) {
    int e = blockIdx.x * blockDim.x + threadIdx.x;
    if (e >= E) return;
    bool i64 = is_i64(ei);
    int s, d; load_edge(ei, E, e, i64, s, d);
    (void)s;
    unsigned long long enc = (1ULL << 40) |
        (unsigned long long)__float2uint_rn(ew[e] * DEG_SCALE);
    atomicAdd(&d_degcnt[d], enc);
}

// ======== K2: bump-alloc row starts + dinv; reset degcnt ===================
__global__ void k_alloc(int N) {
    int n = blockIdx.x * blockDim.x + threadIdx.x;
    if (n >= N) return;
    unsigned long long pc = d_degcnt[n];
    int   cnt = (int)(pc >> 40);
    float deg = (float)(pc & ((1ULL << 40) - 1)) * (1.0f / DEG_SCALE);
    int start = atomicAdd(&d_total, cnt);
    d_cnt[n]    = cnt;
    d_start[n]  = start;
    d_cursor[n] = start;
    d_dinv[n]   = rsqrtf(1.0f + deg);     // self-loop weight 1 => deg >= 1
    d_degcnt[n] = 0ULL;                   // restore for next replay
}

// ======== K3: GEMM g = (x @ W1) * dinv, f32x2 FFMA2 ========================
__device__ __forceinline__ unsigned long long pack2(float a, float b) {
    unsigned long long r;
    asm("mov.b64 %0, {%1, %2};" : "=l"(r) : "f"(a), "f"(b));
    return r;
}
__device__ __forceinline__ void fma2(unsigned long long& d,
                                     unsigned long long a, unsigned long long b) {
    asm("fma.rn.f32x2 %0, %1, %2, %0;" : "+l"(d) : "l"(a), "l"(b));
}
__device__ __forceinline__ void unpack2(unsigned long long v, float& a, float& b) {
    asm("mov.b64 {%0, %1}, %2;" : "=f"(a), "=f"(b) : "l"(v));
}

extern __shared__ float smem_dyn[];
#define GEMM_SMEM ((IN_DIM * HID + IN_DIM * XS_STRIDE) * 4)

__global__ void __launch_bounds__(128, 2)
k_gemm(const float* __restrict__ x, const float* __restrict__ W1, int N) {
    float* Ws = smem_dyn;                       // [128][64]
    float* xs = smem_dyn + IN_DIM * HID;        // [128][XS_STRIDE]
    int tid = threadIdx.x;
    int row0 = blockIdx.x * 128;

    #pragma unroll
    for (int i = 0; i < 16; i++)
        ((float4*)Ws)[tid + i * 128] = ((const float4*)W1)[tid + i * 128];

    #pragma unroll
    for (int i = 0; i < 32; i++) {
        int idx = tid + i * 128;
        int r   = idx >> 5;
        int k4  = idx & 31;
        float4 v = make_float4(0.f, 0.f, 0.f, 0.f);
        int row = row0 + r;
        if (row < N) v = ((const float4*)x)[(size_t)row * 32 + k4];
        float2* p = (float2*)&xs[r * XS_STRIDE + 4 * k4];
        p[0] = make_float2(v.x, v.y);
        p[1] = make_float2(v.z, v.w);
    }
    __syncthreads();

    int cg = tid & 7;       // 8 col groups x 8 cols
    int rg = tid >> 3;      // 16 row groups; thread rows: rg + 16*j
    unsigned long long acc[8][4];
    #pragma unroll
    for (int j = 0; j < 8; j++)
        #pragma unroll
        for (int p = 0; p < 4; p++) acc[j][p] = 0ULL;

    #pragma unroll 2
    for (int k = 0; k < IN_DIM; k++) {
        const unsigned long long* wp =
            (const unsigned long long*)&Ws[k * HID + 8 * cg];
        unsigned long long w0 = wp[0], w1 = wp[1], w2 = wp[2], w3 = wp[3];
        #pragma unroll
        for (int j = 0; j < 8; j++) {
            float xv = xs[(rg + 16 * j) * XS_STRIDE + k];
            unsigned long long xx = pack2(xv, xv);
            fma2(acc[j][0], xx, w0);
            fma2(acc[j][1], xx, w1);
            fma2(acc[j][2], xx, w2);
            fma2(acc[j][3], xx, w3);
        }
    }

    #pragma unroll
    for (int j = 0; j < 8; j++) {
        int row = row0 + rg + 16 * j;
        if (row < N) {
            float di = d_dinv[row];
            float2* dst = (float2*)&d_g[(size_t)row * HID + 8 * cg];
            #pragma unroll
            for (int p = 0; p < 4; p++) {
                float a, b; unpack2(acc[j][p], a, b);
                dst[p] = make_float2(di * a, di * b);
            }
        }
    }
}

// ======== K4: fill CSR ======================================================
__global__ void k_fill(const int* __restrict__ ei,
                       const float* __restrict__ ew, int E) {
    int e = blockIdx.x * blockDim.x + threadIdx.x;
    if (e >= E) return;
    bool i64 = is_i64(ei);
    int s, d; load_edge(ei, E, e, i64, s, d);
    int slot = atomicAdd(&d_cursor[d], 1);
    d_csr[slot] = make_int2(s, __float_as_int(ew[e]));
}

// ======== K5: layer-1 gather + bias + ReLU + @W2, fused ====================
// 16 threads per node, thread c owns float4 column c.
__global__ __launch_bounds__(256)
void k_agg1(const float* __restrict__ b1, const float* __restrict__ W2, int N) {
    int t = blockIdx.x * blockDim.x + threadIdx.x;
    int n = t >> 4;
    int c = t & 15;
    bool valid = (n < N);
    if (!valid) n = 0;

    int st  = d_start[n];
    int cnt = d_cnt[n];
    const float4* g4 = (const float4*)d_g;
    float4 acc = g4[(size_t)n * HID4 + c];          // self-loop term

    int j = 0;
    for (; j + 4 <= cnt; j += 4) {
        int2 e0 = d_csr[st + j];
        int2 e1 = d_csr[st + j + 1];
        int2 e2 = d_csr[st + j + 2];
        int2 e3 = d_csr[st + j + 3];
        float4 v0 = g4[(size_t)e0.x * HID4 + c];
        float4 v1 = g4[(size_t)e1.x * HID4 + c];
        float4 v2 = g4[(size_t)e2.x * HID4 + c];
        float4 v3 = g4[(size_t)e3.x * HID4 + c];
        float w0 = __int_as_float(e0.y), w1 = __int_as_float(e1.y);
        float w2 = __int_as_float(e2.y), w3 = __int_as_float(e3.y);
        acc.x = fmaf(w0, v0.x, fmaf(w1, v1.x, fmaf(w2, v2.x, fmaf(w3, v3.x, acc.x))));
        acc.y = fmaf(w0, v0.y, fmaf(w1, v1.y, fmaf(w2, v2.y, fmaf(w3, v3.y, acc.y))));
        acc.z = fmaf(w0, v0.z, fmaf(w1, v1.z, fmaf(w2, v2.z, fmaf(w3, v3.z, acc.z))));
        acc.w = fmaf(w0, v0.w, fmaf(w1, v1.w, fmaf(w2, v2.w, fmaf(w3, v3.w, acc.w))));
    }
    for (; j < cnt; j++) {
        int2 e = d_csr[st + j];
        float4 v = g4[(size_t)e.x * HID4 + c];
        float w = __int_as_float(e.y);
        acc.x = fmaf(w, v.x, acc.x);
        acc.y = fmaf(w, v.y, acc.y);
        acc.z = fmaf(w, v.z, acc.z);
        acc.w = fmaf(w, v.w, acc.w);
    }

    float di = d_dinv[n];
    float4 bb = ((const float4*)b1)[c];
    float4 v;
    v.x = fmaxf(fmaf(di, acc.x, bb.x), 0.f);
    v.y = fmaxf(fmaf(di, acc.y, bb.y), 0.f);
    v.z = fmaxf(fmaf(di, acc.z, bb.z), 0.f);
    v.w = fmaxf(fmaf(di, acc.w, bb.w), 0.f);
    float4 w2 = ((const float4*)W2)[c];
    float p = v.x * w2.x + v.y * w2.y + v.z * w2.z + v.w * w2.w;
    p += __shfl_xor_sync(0xffffffffu, p, 8);
    p += __shfl_xor_sync(0xffffffffu, p, 4);
    p += __shfl_xor_sync(0xffffffffu, p, 2);
    p += __shfl_xor_sync(0xffffffffu, p, 1);
    if (valid && c == 0) d_g2[n] = p * di;
}

// ======== K6: layer-2 gather + sigmoid + output; resets ====================
// 8 threads per node (4 nodes per warp).
__global__ void k_agg2(const float* __restrict__ b2, float* __restrict__ out, int N) {
    int t = blockIdx.x * blockDim.x + threadIdx.x;
    if (t == 0) d_total = 0;                  // restore for next replay
    int n    = t >> 3;
    int lane = t & 7;
    if (n >= N) return;                       // warp-uniform (N*8 % 32 == 0)
    int st  = d_start[n];
    int cnt = d_cnt[n];
    float acc = 0.f;
    for (int j = lane; j < cnt; j += 8) {
        int2 e = d_csr[st + j];
        acc += __int_as_float(e.y) * d_g2[e.x];
    }
    acc += __shfl_xor_sync(0xffffffffu, acc, 4);
    acc += __shfl_xor_sync(0xffffffffu, acc, 2);
    acc += __shfl_xor_sync(0xffffffffu, acc, 1);
    if (lane == 0) {
        float tt = fmaf(d_dinv[n], acc + d_g2[n], b2[0]);
        out[n] = 1.0f / (1.0f + expf(-tt));
        d_cnt[n] = 0;                         // restore for next replay
    }
}

// ---------------- launcher --------------------------------------------------
extern "C" void kernel_launch(void* const* d_in, const int* in_sizes, int n_in,
                              void* d_out, int out_size) {
    const float* x  = (const float*)d_in[0];
    const int*   ei = (const int*)d_in[1];
    const float* ew = (const float*)d_in[2];
    const float* W1 = (const float*)d_in[3];
    const float* b1 = (const float*)d_in[4];
    const float* W2 = (const float*)d_in[5];
    const float* b2 = (const float*)d_in[6];
    float* out = (float*)d_out;

    int N = in_sizes[0] / IN_DIM;   // 50000
    int E = in_sizes[2];            // 800000

    cudaFuncSetAttribute(k_gemm, cudaFuncAttributeMaxDynamicSharedMemorySize,
                         GEMM_SMEM);

    k_count<<<(E + 255) / 256, 256>>>(ei, ew, E);
    k_alloc<<<(N + 255) / 256, 256>>>(N);
    k_gemm <<<(N + 127) / 128, 128, GEMM_SMEM>>>(x, W1, N);
    k_fill <<<(E + 255) / 256, 256>>>(ei, ew, E);
    k_agg1 <<<(N * 16 + 255) / 256, 256>>>(b1, W2, N);
    k_agg2 <<<(N * 8 + 255) / 256, 256>>>(b2, out, N);
}